// round 4
// baseline (speedup 1.0000x reference)
#include <cuda_runtime.h>
#include <stdint.h>
#include <string.h>

#define N_SEG 128
#define S_VID 2048
#define HDIM  256
#define DDIM  512
#define RTOT  (N_SEG + S_VID)   // 2176
#define NEGV  (-1000.0f)

__device__ float g_P[RTOT * HDIM];          // rows 0..127: A(+b1), rows 128..: B
__device__ float g_logitsT[S_VID * N_SEG];  // [s][n]
__device__ float g_logsigT[S_VID * N_SEG];  // [s][n]

typedef unsigned long long u64;
union U2F { u64 u; float2 f; };

__device__ __forceinline__ u64 dup2(float a) {
    u64 d; asm("mov.b64 %0,{%1,%1};" : "=l"(d) : "f"(a)); return d;
}
__device__ __forceinline__ void unpack2(u64 v, float& lo, float& hi) {
    asm("mov.b64 {%0,%1},%2;" : "=f"(lo), "=f"(hi) : "l"(v));
}
__device__ __forceinline__ void fma2(u64& acc, u64 a, u64 b) {
    asm("fma.rn.f32x2 %0,%1,%2,%0;" : "+l"(acc) : "l"(a), "l"(b));
}
__device__ __forceinline__ u64 add2v(u64 a, u64 b) {
    u64 c; asm("add.rn.f32x2 %0,%1,%2;" : "=l"(c) : "l"(a), "l"(b)); return c;
}

// ============================================================
// K1: P[r][h] = dot(x_r, W1_half_row_h) (+ b1[h] for seg rows)
//   64 rows x 64 h tile, BK=32, 256 threads, 2rows x 8h microtile, f32x2
// ============================================================
__global__ __launch_bounds__(256) void gemm_k1(
    const float* __restrict__ seg, const float* __restrict__ vid,
    const float* __restrict__ W1, const float* __restrict__ b1)
{
    __shared__ float Xs[32][68];
    __shared__ float Ws[32][68];
    const int r0 = blockIdx.x * 64;
    const int h0 = blockIdx.y * 64;
    const int t  = threadIdx.x;
    const int tm = (t >> 3) * 2;   // 0..62 rows (32 groups)
    const int tn = (t & 7) * 8;    // 0..56 h    (8 groups)
    const int koff = (r0 < N_SEG) ? 0 : DDIM;
    const float* xbase = (r0 < N_SEG) ? (seg + (size_t)r0 * DDIM)
                                      : (vid + (size_t)(r0 - N_SEG) * DDIM);

    u64 acc[2][4];
    #pragma unroll
    for (int i = 0; i < 2; i++)
        #pragma unroll
        for (int j = 0; j < 4; j++) acc[i][j] = 0ull;

    float4 xreg[2], wreg[2];
    #pragma unroll
    for (int p = 0; p < 2; p++) {
        int idx = t + p * 256;
        int rr = idx >> 3, fq = idx & 7;
        xreg[p] = *(const float4*)(xbase + (size_t)rr * DDIM + 4 * fq);
        wreg[p] = *(const float4*)(W1 + (size_t)(h0 + rr) * (2 * DDIM) + koff + 4 * fq);
    }

    for (int k0 = 0; k0 < DDIM; k0 += 32) {
        __syncthreads();
        #pragma unroll
        for (int p = 0; p < 2; p++) {
            int idx = t + p * 256;
            int rr = idx >> 3, fq = idx & 7;
            int col = rr ^ (4 * fq);
            Xs[4 * fq + 0][col] = xreg[p].x;
            Xs[4 * fq + 1][col] = xreg[p].y;
            Xs[4 * fq + 2][col] = xreg[p].z;
            Xs[4 * fq + 3][col] = xreg[p].w;
            Ws[4 * fq + 0][col] = wreg[p].x;
            Ws[4 * fq + 1][col] = wreg[p].y;
            Ws[4 * fq + 2][col] = wreg[p].z;
            Ws[4 * fq + 3][col] = wreg[p].w;
        }
        __syncthreads();
        if (k0 + 32 < DDIM) {
            #pragma unroll
            for (int p = 0; p < 2; p++) {
                int idx = t + p * 256;
                int rr = idx >> 3, fq = idx & 7;
                xreg[p] = *(const float4*)(xbase + (size_t)rr * DDIM + k0 + 32 + 4 * fq);
                wreg[p] = *(const float4*)(W1 + (size_t)(h0 + rr) * (2 * DDIM) + koff + k0 + 32 + 4 * fq);
            }
        }
        #pragma unroll
        for (int kk = 0; kk < 32; kk++) {
            int q4 = 4 * (kk >> 2);
            float2 av = *(const float2*)&Xs[kk][tm ^ q4];
            ulonglong2 w0 = *(const ulonglong2*)&Ws[kk][tn ^ q4];
            ulonglong2 w1 = *(const ulonglong2*)&Ws[kk][(tn + 4) ^ q4];
            u64 a0 = dup2(av.x), a1 = dup2(av.y);
            fma2(acc[0][0], a0, w0.x); fma2(acc[0][1], a0, w0.y);
            fma2(acc[0][2], a0, w1.x); fma2(acc[0][3], a0, w1.y);
            fma2(acc[1][0], a1, w0.x); fma2(acc[1][1], a1, w0.y);
            fma2(acc[1][2], a1, w1.x); fma2(acc[1][3], a1, w1.y);
        }
    }

    #pragma unroll
    for (int i = 0; i < 2; i++) {
        int r = r0 + tm + i;
        #pragma unroll
        for (int jp = 0; jp < 4; jp++) {
            float v0, v1;
            unpack2(acc[i][jp], v0, v1);
            int h = h0 + tn + 2 * jp;
            if (r0 < N_SEG) { v0 += b1[h]; v1 += b1[h + 1]; }
            *(float2*)&g_P[(size_t)r * HDIM + h] = make_float2(v0, v1);
        }
    }
}

// ============================================================
// K2: logitsT[s][n] = sum_h relu(A'[n][h] + B[s][h]) * W2[h] + b2
//   64 n x 32 s tile, BK=32, 512 threads, 2n x 2s microtile, f32x2 math
// ============================================================
__global__ __launch_bounds__(512) void fused_k2(
    const float* __restrict__ W2, const float* __restrict__ b2)
{
    __shared__ float As[32][68];   // 64 n
    __shared__ float Bs[32][36];   // 32 s
    __shared__ float w2s[32];
    const int n0 = blockIdx.x * 64;   // grid.x = 2
    const int s0 = blockIdx.y * 32;   // grid.y = 64
    const int t  = threadIdx.x;
    const int tn = (t & 31) * 2;      // lanes span n
    const int ts = (t >> 5) * 2;
    const int rr = t >> 3, fq = t & 7;
    const float bb2 = b2[0];

    u64 acc0 = 0ull, acc1 = 0ull;   // pairs over s, for n = tn, tn+1

    float4 areg, breg; float wreg = 0.f;
    areg = *(const float4*)(g_P + (size_t)(n0 + rr) * HDIM + 4 * fq);
    if (t < 256) breg = *(const float4*)(g_P + (size_t)(N_SEG + s0 + rr) * HDIM + 4 * fq);
    if (t < 32)  wreg = W2[t];

    for (int k0 = 0; k0 < HDIM; k0 += 32) {
        __syncthreads();
        {
            int col = rr ^ (4 * fq);
            As[4 * fq + 0][col] = areg.x;
            As[4 * fq + 1][col] = areg.y;
            As[4 * fq + 2][col] = areg.z;
            As[4 * fq + 3][col] = areg.w;
            if (t < 256) {
                Bs[4 * fq + 0][col] = breg.x;
                Bs[4 * fq + 1][col] = breg.y;
                Bs[4 * fq + 2][col] = breg.z;
                Bs[4 * fq + 3][col] = breg.w;
            }
            if (t < 32) w2s[t] = wreg;
        }
        __syncthreads();
        if (k0 + 32 < HDIM) {
            areg = *(const float4*)(g_P + (size_t)(n0 + rr) * HDIM + k0 + 32 + 4 * fq);
            if (t < 256) breg = *(const float4*)(g_P + (size_t)(N_SEG + s0 + rr) * HDIM + k0 + 32 + 4 * fq);
            if (t < 32)  wreg = W2[k0 + 32 + t];
        }
        #pragma unroll
        for (int kk = 0; kk < 32; kk++) {
            int q4 = 4 * (kk >> 2);
            float2 an = *(const float2*)&As[kk][tn ^ q4];
            U2F bv; bv.f = *(const float2*)&Bs[kk][ts ^ q4];
            u64 wd = dup2(w2s[kk]);
            U2F c0, c1;
            c0.u = add2v(dup2(an.x), bv.u);
            c1.u = add2v(dup2(an.y), bv.u);
            c0.f.x = fmaxf(c0.f.x, 0.0f); c0.f.y = fmaxf(c0.f.y, 0.0f);
            c1.f.x = fmaxf(c1.f.x, 0.0f); c1.f.y = fmaxf(c1.f.y, 0.0f);
            fma2(acc0, c0.u, wd);
            fma2(acc1, c1.u, wd);
        }
    }

    float L00, L01, L10, L11;   // L[n][s_off]
    unpack2(acc0, L00, L01);
    unpack2(acc1, L10, L11);
    L00 += bb2; L01 += bb2; L10 += bb2; L11 += bb2;
    #pragma unroll
    for (int j = 0; j < 2; j++) {
        int s = s0 + ts + j;
        float La = j ? L01 : L00;
        float Lb = j ? L11 : L10;
        *(float2*)&g_logitsT[(size_t)s * N_SEG + n0 + tn] = make_float2(La, Lb);
        float lsa = fminf(La, 0.0f) - __logf(1.0f + __expf(-fabsf(La)));
        float lsb = fminf(Lb, 0.0f) - __logf(1.0f + __expf(-fabsf(Lb)));
        *(float2*)&g_logsigT[(size_t)s * N_SEG + n0 + tn] = make_float2(lsa, lsb);
    }
}

// ============================================================
// K3 pipeline: warp0 = serial DP (stores col state, no bit ops)
//              warps 1-3 = gmem->smem logsig loader
//              warps 4-7 = take-bit recompute (one chunk behind)
// ============================================================
template<bool CLAMP>
__device__ __forceinline__ void dp_chunk(const float* __restrict__ buf,
                                         float* __restrict__ colc, int c, int L,
                                         float& p0, float& p1, float& p2, float& p3)
{
    const int n0 = 4 * L;
    #pragma unroll 8
    for (int i = 31; i >= 0; i--) {
        float4 ls = *(const float4*)(buf + i * 128 + n0);
        float nxt3 = __shfl_down_sync(0xffffffffu, p0, 1);
        if (L == 31) nxt3 = 0.0f;               // n=127 adds 0
        float c0 = ls.x + p1;
        float c1 = ls.y + p2;
        float c2 = ls.z + p3;
        float c3 = ls.w + nxt3;
        float v0 = fmaxf(c0, p0);
        float v1 = fmaxf(c1, p1);
        float v2 = fmaxf(c2, p2);
        float v3 = fmaxf(c3, p3);
        if (CLAMP) {
            int s = c * 32 + i;
            v0 = (s >= n0     && s <= 1920 + n0) ? v0 : NEGV;
            v1 = (s >= n0 + 1 && s <= 1921 + n0) ? v1 : NEGV;
            v2 = (s >= n0 + 2 && s <= 1922 + n0) ? v2 : NEGV;
            v3 = (s >= n0 + 3 && s <= 1923 + n0) ? v3 : NEGV;
        }
        p0 = v0; p1 = v1; p2 = v2; p3 = v3;
        *(float4*)(colc + i * 128 + n0) = make_float4(p0, p1, p2, p3);
    }
}

__device__ __forceinline__ void load_chunk(const float4* __restrict__ src,
                                           float4* __restrict__ dst, int lt)
{
    #pragma unroll
    for (int j = 0; j < 11; j++) {
        int i = lt + 96 * j;
        if (i < 1024) dst[i] = src[i];
    }
}

// take(s,n) = (logsig(s,n) + (n<127 ? col(s+1)[n+1] : 0)) >= col(s+1)[n]
__device__ __forceinline__ void take_chunk(const float* __restrict__ lsc,
                                           const float* __restrict__ colc,
                                           const float* __restrict__ bound0,
                                           int cc, int n, unsigned* __restrict__ rowbits)
{
    unsigned word = 0;
    #pragma unroll 8
    for (int i = 0; i < 31; i++) {
        const float* row = colc + (i + 1) * 128;
        float prev = row[n];
        float nxt  = (n == 127) ? 0.0f : row[n + 1];
        float curr = lsc[i * 128 + n] + nxt;
        if (curr >= prev) word |= (1u << i);
    }
    {
        float prev = bound0[n];
        float nxt  = (n == 127) ? 0.0f : bound0[n + 1];
        float curr = lsc[31 * 128 + n] + nxt;
        if (curr >= prev) word |= (1u << 31);
    }
    rowbits[cc * 128 + n] = word;
}

__global__ __launch_bounds__(256) void dp_k3(float* __restrict__ out, int out_size)
{
    extern __shared__ unsigned char smraw[];
    float*    lsbuf    = (float*)smraw;                      // [4][4096]
    float*    colbuf   = lsbuf + 4 * 4096;                   // [3][4096]
    unsigned* rowbits  = (unsigned*)(colbuf + 3 * 4096);     // [64][128]
    int*      alignArr = (int*)(rowbits + 64 * 128);         // [128]
    float*    redbuf   = (float*)(alignArr + 128);           // [4]

    const int t = threadIdx.x;
    const int L = t & 31;

    if (t < 128) alignArr[t] = 0;
    if (t >= 128) colbuf[1 * 4096 + (t - 128)] = NEGV;  // init boundary col(2048) in slot1 row0
    if (t >= 32 && t < 128) {
        load_chunk((const float4*)(g_logsigT + 63 * 4096), (float4*)(lsbuf + 3 * 4096), t - 32);
        load_chunk((const float4*)(g_logsigT + 62 * 4096), (float4*)(lsbuf + 2 * 4096), t - 32);
    }
    __syncthreads();

    float p0 = NEGV, p1 = NEGV, p2 = NEGV, p3 = NEGV;
    for (int c = 63; c >= 0; c--) {
        if (t < 32) {
            const float* ls = lsbuf + (c & 3) * 4096;
            float* colc = colbuf + (c % 3) * 4096;
            if (c >= 4 && c <= 59) dp_chunk<false>(ls, colc, c, L, p0, p1, p2, p3);
            else                   dp_chunk<true >(ls, colc, c, L, p0, p1, p2, p3);
        } else if (t < 128) {
            if (c >= 2)
                load_chunk((const float4*)(g_logsigT + (size_t)(c - 2) * 4096),
                           (float4*)(lsbuf + ((c - 2) & 3) * 4096), t - 32);
        } else {
            if (c < 63) {
                int cc = c + 1;
                take_chunk(lsbuf + (cc & 3) * 4096, colbuf + (cc % 3) * 4096,
                           colbuf + ((cc + 1) % 3) * 4096, cc, t - 128, rowbits);
            }
        }
        __syncthreads();
    }
    // epilogue: take bits for chunk 0
    if (t >= 128) {
        take_chunk(lsbuf + 0 * 4096, colbuf + 0 * 4096,
                   colbuf + 1 * 4096, 0, t - 128, rowbits);
    }
    __syncthreads();

    // walk
    if (t == 0) {
        int scur = 0;
        for (int n = 0; n < 128; n++) {
            int w = scur >> 5;
            unsigned word = rowbits[w * 128 + n] & (0xFFFFFFFFu << (scur & 31));
            while (word == 0) {
                w++;
                if (w >= 64) break;
                word = rowbits[w * 128 + n];
            }
            if (w >= 64) break;
            int s = w * 32 + (__ffs(word) - 1);
            alignArr[n] = s;
            scur = s + 1;
            if (scur >= S_VID) break;
        }
    }
    __syncthreads();

    // outputs
    if (t < 128) {
        int a = alignArr[t];
        out[(size_t)(S_VID + t) * RTOT + a] = 1.0f;
        float v = g_logitsT[(size_t)a * N_SEG + t];
        #pragma unroll
        for (int o = 16; o; o >>= 1) v += __shfl_down_sync(0xffffffffu, v, o);
        if (L == 0) redbuf[t >> 5] = v;
    }
    __syncthreads();
    if (t == 0) {
        float sum = redbuf[0] + redbuf[1] + redbuf[2] + redbuf[3];
        if (out_size > RTOT * RTOT) out[(size_t)RTOT * RTOT] = sum * (1.0f / 128.0f);
    }
}

// ============================================================
extern "C" void kernel_launch(void* const* d_in, const int* in_sizes, int n_in,
                              void* d_out, int out_size)
{
    const float* seg = (const float*)d_in[0];
    const float* vid = (const float*)d_in[1];
    const float* W1  = (const float*)d_in[2];
    const float* b1  = (const float*)d_in[3];
    const float* W2  = (const float*)d_in[4];
    const float* b2  = (const float*)d_in[5];
    float* out = (float*)d_out;

    cudaMemsetAsync(out, 0, (size_t)out_size * sizeof(float), 0);
    gemm_k1<<<dim3(34, 4), 256>>>(seg, vid, W1, b1);
    fused_k2<<<dim3(2, 64), 512>>>(W2, b2);

    const int smem_k3 = (4 * 4096 + 3 * 4096) * 4 + 64 * 128 * 4 + 128 * 4 + 4 * 4;
    cudaFuncSetAttribute(dp_k3, cudaFuncAttributeMaxDynamicSharedMemorySize, smem_k3);
    dp_k3<<<1, 256, smem_k3>>>(out, out_size);
}

// round 5
// speedup vs baseline: 1.0811x; 1.0811x over previous
#include <cuda_runtime.h>
#include <stdint.h>

#define N_SEG 128
#define S_VID 2048
#define HDIM  256
#define DDIM  512
#define RTOT  (N_SEG + S_VID)   // 2176
#define NEGV  (-1000.0f)

__device__ float g_P[RTOT * HDIM];          // rows 0..127: A(+b1), rows 128..: B
__device__ float g_logitsT[S_VID * N_SEG];  // [s][n]
__device__ float g_logsigT[S_VID * N_SEG];  // [s][n]

typedef unsigned long long u64;

__device__ __forceinline__ u64 dup2(float a) {
    u64 d; asm("mov.b64 %0,{%1,%1};" : "=l"(d) : "f"(a)); return d;
}
__device__ __forceinline__ void unpack2(u64 v, float& lo, float& hi) {
    asm("mov.b64 {%0,%1},%2;" : "=f"(lo), "=f"(hi) : "l"(v));
}
__device__ __forceinline__ void fma2(u64& acc, u64 a, u64 b) {
    asm("fma.rn.f32x2 %0,%1,%2,%0;" : "+l"(acc) : "l"(a), "l"(b));
}

// ============================================================
// K1 (R3 config): 64 rows x 64 h, BK=32, 512 threads, 2x4 microtile, f32x2
// ============================================================
__global__ __launch_bounds__(512) void gemm_k1(
    const float* __restrict__ seg, const float* __restrict__ vid,
    const float* __restrict__ W1, const float* __restrict__ b1)
{
    __shared__ float Xs[32][68];
    __shared__ float Ws[32][68];
    const int r0 = blockIdx.x * 64;
    const int h0 = blockIdx.y * 64;
    const int t  = threadIdx.x;
    const int tm = (t >> 4) * 2;
    const int tn = (t & 15) * 4;
    const int koff = (r0 < N_SEG) ? 0 : DDIM;
    const float* xbase = (r0 < N_SEG) ? (seg + (size_t)r0 * DDIM)
                                      : (vid + (size_t)(r0 - N_SEG) * DDIM);
    const int rr = t >> 3, fq = t & 7;

    u64 acc[2][2];
    acc[0][0] = acc[0][1] = acc[1][0] = acc[1][1] = 0ull;

    float4 xreg, wreg;
    xreg = *(const float4*)(xbase + (size_t)rr * DDIM + 4 * fq);
    wreg = *(const float4*)(W1 + (size_t)(h0 + rr) * (2 * DDIM) + koff + 4 * fq);

    for (int k0 = 0; k0 < DDIM; k0 += 32) {
        __syncthreads();
        {
            int col = rr ^ (4 * fq);
            Xs[4 * fq + 0][col] = xreg.x;
            Xs[4 * fq + 1][col] = xreg.y;
            Xs[4 * fq + 2][col] = xreg.z;
            Xs[4 * fq + 3][col] = xreg.w;
            Ws[4 * fq + 0][col] = wreg.x;
            Ws[4 * fq + 1][col] = wreg.y;
            Ws[4 * fq + 2][col] = wreg.z;
            Ws[4 * fq + 3][col] = wreg.w;
        }
        __syncthreads();
        if (k0 + 32 < DDIM) {
            xreg = *(const float4*)(xbase + (size_t)rr * DDIM + k0 + 32 + 4 * fq);
            wreg = *(const float4*)(W1 + (size_t)(h0 + rr) * (2 * DDIM) + koff + k0 + 32 + 4 * fq);
        }
        #pragma unroll
        for (int kk = 0; kk < 32; kk++) {
            int q4 = 4 * (kk >> 2);
            float2 av = *(const float2*)&Xs[kk][tm ^ q4];
            ulonglong2 wv = *(const ulonglong2*)&Ws[kk][tn ^ q4];
            u64 a0 = dup2(av.x), a1 = dup2(av.y);
            fma2(acc[0][0], a0, wv.x); fma2(acc[0][1], a0, wv.y);
            fma2(acc[1][0], a1, wv.x); fma2(acc[1][1], a1, wv.y);
        }
    }

    #pragma unroll
    for (int i = 0; i < 2; i++) {
        int r = r0 + tm + i;
        #pragma unroll
        for (int jp = 0; jp < 2; jp++) {
            float v0, v1;
            unpack2(acc[i][jp], v0, v1);
            int h = h0 + tn + 2 * jp;
            if (r0 < N_SEG) { v0 += b1[h]; v1 += b1[h + 1]; }
            *(float2*)&g_P[(size_t)r * HDIM + h] = make_float2(v0, v1);
        }
    }
}

// ============================================================
// K2 (R3 config): 64 n x 32 s, BK=32, 512 threads, 2x2 scalar microtile
// ============================================================
__global__ __launch_bounds__(512) void fused_k2(
    const float* __restrict__ W2, const float* __restrict__ b2)
{
    __shared__ float As[32][68];
    __shared__ float Bs[32][36];
    __shared__ float w2s[32];
    const int n0 = blockIdx.x * 64;
    const int s0 = blockIdx.y * 32;
    const int t  = threadIdx.x;
    const int tn = (t & 31) * 2;
    const int ts = (t >> 5) * 2;
    const int rr = t >> 3, fq = t & 7;
    const float bb2 = b2[0];

    float acc00 = 0.f, acc01 = 0.f, acc10 = 0.f, acc11 = 0.f;

    float4 areg, breg; float wreg = 0.f;
    areg = *(const float4*)(g_P + (size_t)(n0 + rr) * HDIM + 4 * fq);
    if (t < 256) breg = *(const float4*)(g_P + (size_t)(N_SEG + s0 + rr) * HDIM + 4 * fq);
    if (t < 32)  wreg = W2[t];

    for (int k0 = 0; k0 < HDIM; k0 += 32) {
        __syncthreads();
        {
            int col = rr ^ (4 * fq);
            As[4 * fq + 0][col] = areg.x;
            As[4 * fq + 1][col] = areg.y;
            As[4 * fq + 2][col] = areg.z;
            As[4 * fq + 3][col] = areg.w;
            if (t < 256) {
                Bs[4 * fq + 0][col] = breg.x;
                Bs[4 * fq + 1][col] = breg.y;
                Bs[4 * fq + 2][col] = breg.z;
                Bs[4 * fq + 3][col] = breg.w;
            }
            if (t < 32) w2s[t] = wreg;
        }
        __syncthreads();
        if (k0 + 32 < HDIM) {
            areg = *(const float4*)(g_P + (size_t)(n0 + rr) * HDIM + k0 + 32 + 4 * fq);
            if (t < 256) breg = *(const float4*)(g_P + (size_t)(N_SEG + s0 + rr) * HDIM + k0 + 32 + 4 * fq);
            if (t < 32)  wreg = W2[k0 + 32 + t];
        }
        #pragma unroll
        for (int kk = 0; kk < 32; kk++) {
            int q4 = 4 * (kk >> 2);
            float2 an = *(const float2*)&As[kk][tn ^ q4];
            float2 bv = *(const float2*)&Bs[kk][ts ^ q4];
            float w = w2s[kk];
            acc00 += fmaxf(an.x + bv.x, 0.0f) * w;
            acc01 += fmaxf(an.x + bv.y, 0.0f) * w;
            acc10 += fmaxf(an.y + bv.x, 0.0f) * w;
            acc11 += fmaxf(an.y + bv.y, 0.0f) * w;
        }
    }

    float L[2][2] = {{acc00 + bb2, acc01 + bb2}, {acc10 + bb2, acc11 + bb2}};
    #pragma unroll
    for (int j = 0; j < 2; j++) {
        int s = s0 + ts + j;
        float L0 = L[0][j], L1 = L[1][j];
        *(float2*)&g_logitsT[(size_t)s * N_SEG + n0 + tn] = make_float2(L0, L1);
        float ls0 = fminf(L0, 0.0f) - __logf(1.0f + __expf(-fabsf(L0)));
        float ls1 = fminf(L1, 0.0f) - __logf(1.0f + __expf(-fabsf(L1)));
        *(float2*)&g_logsigT[(size_t)s * N_SEG + n0 + tn] = make_float2(ls0, ls1);
    }
}

// ============================================================
// K3 pipeline (priority-fixed roles, 256 threads):
//   warps 0-3 (t<128)    : take-bit recompute (one chunk behind)
//   warps 4-6 (128..223) : gmem->smem logsig loader (two chunks ahead)
//   warp  7  (224..255)  : serial DP (HIGHEST wid -> wins SMSP arbitration)
// ============================================================
template<bool CLAMP>
__device__ __forceinline__ void dp_chunk(const float* __restrict__ buf,
                                         float* __restrict__ colc, int c, int L,
                                         float& p0, float& p1, float& p2, float& p3)
{
    const int n0 = 4 * L;
    #pragma unroll 8
    for (int i = 31; i >= 0; i--) {
        float4 ls = *(const float4*)(buf + i * 128 + n0);
        float nxt3 = __shfl_down_sync(0xffffffffu, p0, 1);
        if (L == 31) nxt3 = 0.0f;               // n=127 adds 0
        float c0 = ls.x + p1;
        float c1 = ls.y + p2;
        float c2 = ls.z + p3;
        float c3 = ls.w + nxt3;
        float v0 = fmaxf(c0, p0);
        float v1 = fmaxf(c1, p1);
        float v2 = fmaxf(c2, p2);
        float v3 = fmaxf(c3, p3);
        if (CLAMP) {
            int s = c * 32 + i;
            v0 = (s >= n0     && s <= 1920 + n0) ? v0 : NEGV;
            v1 = (s >= n0 + 1 && s <= 1921 + n0) ? v1 : NEGV;
            v2 = (s >= n0 + 2 && s <= 1922 + n0) ? v2 : NEGV;
            v3 = (s >= n0 + 3 && s <= 1923 + n0) ? v3 : NEGV;
        }
        p0 = v0; p1 = v1; p2 = v2; p3 = v3;
        *(float4*)(colc + i * 128 + n0) = make_float4(p0, p1, p2, p3);
    }
}

__device__ __forceinline__ void load_chunk(const float4* __restrict__ src,
                                           float4* __restrict__ dst, int lt)
{
    #pragma unroll
    for (int j = 0; j < 11; j++) {
        int i = lt + 96 * j;
        if (i < 1024) dst[i] = src[i];
    }
}

// take(s,n) = (logsig(s,n) + (n<127 ? col(s+1)[n+1] : 0)) >= col(s+1)[n]
__device__ __forceinline__ void take_chunk(const float* __restrict__ lsc,
                                           const float* __restrict__ colc,
                                           const float* __restrict__ bound0,
                                           int cc, int n, unsigned* __restrict__ rowbits)
{
    unsigned word = 0;
    #pragma unroll 8
    for (int i = 0; i < 31; i++) {
        const float* row = colc + (i + 1) * 128;
        float prev = row[n];
        float nxt  = (n == 127) ? 0.0f : row[n + 1];
        float curr = lsc[i * 128 + n] + nxt;
        if (curr >= prev) word |= (1u << i);
    }
    {
        float prev = bound0[n];
        float nxt  = (n == 127) ? 0.0f : bound0[n + 1];
        float curr = lsc[31 * 128 + n] + nxt;
        if (curr >= prev) word |= (1u << 31);
    }
    rowbits[cc * 128 + n] = word;
}

__global__ __launch_bounds__(256) void dp_k3(float* __restrict__ out, int out_size)
{
    extern __shared__ unsigned char smraw[];
    float*    lsbuf    = (float*)smraw;                      // [4][4096]
    float*    colbuf   = lsbuf + 4 * 4096;                   // [3][4096]
    unsigned* rowbits  = (unsigned*)(colbuf + 3 * 4096);     // [64][128]
    int*      alignArr = (int*)(rowbits + 64 * 128);         // [128]
    float*    redbuf   = (float*)(alignArr + 128);           // [4]

    const int t = threadIdx.x;

    if (t < 128) {
        alignArr[t] = 0;
        colbuf[1 * 4096 + t] = NEGV;   // boundary col(2048) lives in slot (63+1)%3 = 1
    }
    if (t >= 128 && t < 224) {
        load_chunk((const float4*)(g_logsigT + 63 * 4096), (float4*)(lsbuf + 3 * 4096), t - 128);
        load_chunk((const float4*)(g_logsigT + 62 * 4096), (float4*)(lsbuf + 2 * 4096), t - 128);
    }
    __syncthreads();

    float p0 = NEGV, p1 = NEGV, p2 = NEGV, p3 = NEGV;
    for (int c = 63; c >= 0; c--) {
        if (t >= 224) {
            const int L = t - 224;
            const float* ls = lsbuf + (c & 3) * 4096;
            float* colc = colbuf + (c % 3) * 4096;
            if (c >= 4 && c <= 59) dp_chunk<false>(ls, colc, c, L, p0, p1, p2, p3);
            else                   dp_chunk<true >(ls, colc, c, L, p0, p1, p2, p3);
        } else if (t >= 128) {
            if (c >= 2)
                load_chunk((const float4*)(g_logsigT + (size_t)(c - 2) * 4096),
                           (float4*)(lsbuf + ((c - 2) & 3) * 4096), t - 128);
        } else {
            if (c < 63) {
                int cc = c + 1;
                take_chunk(lsbuf + (cc & 3) * 4096, colbuf + (cc % 3) * 4096,
                           colbuf + ((cc + 1) % 3) * 4096, cc, t, rowbits);
            }
        }
        __syncthreads();
    }
    // epilogue: take bits for chunk 0
    if (t < 128) {
        take_chunk(lsbuf + 0 * 4096, colbuf + 0 * 4096,
                   colbuf + 1 * 4096, 0, t, rowbits);
    }
    __syncthreads();

    // walk
    if (t == 0) {
        int scur = 0;
        for (int n = 0; n < 128; n++) {
            int w = scur >> 5;
            unsigned word = rowbits[w * 128 + n] & (0xFFFFFFFFu << (scur & 31));
            while (word == 0) {
                w++;
                if (w >= 64) break;
                word = rowbits[w * 128 + n];
            }
            if (w >= 64) break;
            int s = w * 32 + (__ffs(word) - 1);
            alignArr[n] = s;
            scur = s + 1;
            if (scur >= S_VID) break;
        }
    }
    __syncthreads();

    // outputs
    if (t < 128) {
        int a = alignArr[t];
        out[(size_t)(S_VID + t) * RTOT + a] = 1.0f;
        float v = g_logitsT[(size_t)a * N_SEG + t];
        #pragma unroll
        for (int o = 16; o; o >>= 1) v += __shfl_down_sync(0xffffffffu, v, o);
        if ((t & 31) == 0) redbuf[t >> 5] = v;
    }
    __syncthreads();
    if (t == 0) {
        float sum = redbuf[0] + redbuf[1] + redbuf[2] + redbuf[3];
        if (out_size > RTOT * RTOT) out[(size_t)RTOT * RTOT] = sum * (1.0f / 128.0f);
    }
}

// ============================================================
extern "C" void kernel_launch(void* const* d_in, const int* in_sizes, int n_in,
                              void* d_out, int out_size)
{
    const float* seg = (const float*)d_in[0];
    const float* vid = (const float*)d_in[1];
    const float* W1  = (const float*)d_in[2];
    const float* b1  = (const float*)d_in[3];
    const float* W2  = (const float*)d_in[4];
    const float* b2  = (const float*)d_in[5];
    float* out = (float*)d_out;

    cudaMemsetAsync(out, 0, (size_t)out_size * sizeof(float), 0);
    gemm_k1<<<dim3(34, 4), 512>>>(seg, vid, W1, b1);
    fused_k2<<<dim3(2, 64), 512>>>(W2, b2);

    const int smem_k3 = (4 * 4096 + 3 * 4096) * 4 + 64 * 128 * 4 + 128 * 4 + 4 * 4;
    cudaFuncSetAttribute(dp_k3, cudaFuncAttributeMaxDynamicSharedMemorySize, smem_k3);
    dp_k3<<<1, 256, smem_k3>>>(out, out_size);
}

// round 6
// speedup vs baseline: 1.3621x; 1.2600x over previous
#include <cuda_runtime.h>
#include <stdint.h>

#define N_SEG 128
#define S_VID 2048
#define HDIM  256
#define DDIM  512
#define RTOT  (N_SEG + S_VID)   // 2176
#define NEGV  (-1000.0f)

__device__ float g_P[RTOT * HDIM];          // rows 0..127: A(+b1), rows 128..: B
__device__ float g_logitsT[S_VID * N_SEG];  // [s][n]
__device__ float g_logsigT[S_VID * N_SEG];  // [s][n]

typedef unsigned long long u64;

__device__ __forceinline__ u64 dup2(float a) {
    u64 d; asm("mov.b64 %0,{%1,%1};" : "=l"(d) : "f"(a)); return d;
}
__device__ __forceinline__ void unpack2(u64 v, float& lo, float& hi) {
    asm("mov.b64 {%0,%1},%2;" : "=f"(lo), "=f"(hi) : "l"(v));
}
__device__ __forceinline__ void fma2(u64& acc, u64 a, u64 b) {
    asm("fma.rn.f32x2 %0,%1,%2,%0;" : "+l"(acc) : "l"(a), "l"(b));
}

// trivial kernel used only to shift ncu's capture window onto dp_k3
__global__ void dummy_k() {}

// ============================================================
// K1: 64 rows x 64 h, BK=32, 512 threads, 2x4 microtile, f32x2
// ============================================================
__global__ __launch_bounds__(512) void gemm_k1(
    const float* __restrict__ seg, const float* __restrict__ vid,
    const float* __restrict__ W1, const float* __restrict__ b1)
{
    __shared__ float Xs[32][68];
    __shared__ float Ws[32][68];
    const int r0 = blockIdx.x * 64;
    const int h0 = blockIdx.y * 64;
    const int t  = threadIdx.x;
    const int tm = (t >> 4) * 2;
    const int tn = (t & 15) * 4;
    const int koff = (r0 < N_SEG) ? 0 : DDIM;
    const float* xbase = (r0 < N_SEG) ? (seg + (size_t)r0 * DDIM)
                                      : (vid + (size_t)(r0 - N_SEG) * DDIM);
    const int rr = t >> 3, fq = t & 7;

    u64 acc[2][2];
    acc[0][0] = acc[0][1] = acc[1][0] = acc[1][1] = 0ull;

    float4 xreg, wreg;
    xreg = *(const float4*)(xbase + (size_t)rr * DDIM + 4 * fq);
    wreg = *(const float4*)(W1 + (size_t)(h0 + rr) * (2 * DDIM) + koff + 4 * fq);

    for (int k0 = 0; k0 < DDIM; k0 += 32) {
        __syncthreads();
        {
            int col = rr ^ (4 * fq);
            Xs[4 * fq + 0][col] = xreg.x;
            Xs[4 * fq + 1][col] = xreg.y;
            Xs[4 * fq + 2][col] = xreg.z;
            Xs[4 * fq + 3][col] = xreg.w;
            Ws[4 * fq + 0][col] = wreg.x;
            Ws[4 * fq + 1][col] = wreg.y;
            Ws[4 * fq + 2][col] = wreg.z;
            Ws[4 * fq + 3][col] = wreg.w;
        }
        __syncthreads();
        if (k0 + 32 < DDIM) {
            xreg = *(const float4*)(xbase + (size_t)rr * DDIM + k0 + 32 + 4 * fq);
            wreg = *(const float4*)(W1 + (size_t)(h0 + rr) * (2 * DDIM) + koff + k0 + 32 + 4 * fq);
        }
        #pragma unroll
        for (int kk = 0; kk < 32; kk++) {
            int q4 = 4 * (kk >> 2);
            float2 av = *(const float2*)&Xs[kk][tm ^ q4];
            ulonglong2 wv = *(const ulonglong2*)&Ws[kk][tn ^ q4];
            u64 a0 = dup2(av.x), a1 = dup2(av.y);
            fma2(acc[0][0], a0, wv.x); fma2(acc[0][1], a0, wv.y);
            fma2(acc[1][0], a1, wv.x); fma2(acc[1][1], a1, wv.y);
        }
    }

    #pragma unroll
    for (int i = 0; i < 2; i++) {
        int r = r0 + tm + i;
        #pragma unroll
        for (int jp = 0; jp < 2; jp++) {
            float v0, v1;
            unpack2(acc[i][jp], v0, v1);
            int h = h0 + tn + 2 * jp;
            if (r0 < N_SEG) { v0 += b1[h]; v1 += b1[h + 1]; }
            *(float2*)&g_P[(size_t)r * HDIM + h] = make_float2(v0, v1);
        }
    }
}

// ============================================================
// K2: 64 n x 32 s, BK=32, 512 threads, 2x2 scalar microtile
// ============================================================
__global__ __launch_bounds__(512) void fused_k2(
    const float* __restrict__ W2, const float* __restrict__ b2)
{
    __shared__ float As[32][68];
    __shared__ float Bs[32][36];
    __shared__ float w2s[32];
    const int n0 = blockIdx.x * 64;
    const int s0 = blockIdx.y * 32;
    const int t  = threadIdx.x;
    const int tn = (t & 31) * 2;
    const int ts = (t >> 5) * 2;
    const int rr = t >> 3, fq = t & 7;
    const float bb2 = b2[0];

    float acc00 = 0.f, acc01 = 0.f, acc10 = 0.f, acc11 = 0.f;

    float4 areg, breg; float wreg = 0.f;
    areg = *(const float4*)(g_P + (size_t)(n0 + rr) * HDIM + 4 * fq);
    if (t < 256) breg = *(const float4*)(g_P + (size_t)(N_SEG + s0 + rr) * HDIM + 4 * fq);
    if (t < 32)  wreg = W2[t];

    for (int k0 = 0; k0 < HDIM; k0 += 32) {
        __syncthreads();
        {
            int col = rr ^ (4 * fq);
            As[4 * fq + 0][col] = areg.x;
            As[4 * fq + 1][col] = areg.y;
            As[4 * fq + 2][col] = areg.z;
            As[4 * fq + 3][col] = areg.w;
            if (t < 256) {
                Bs[4 * fq + 0][col] = breg.x;
                Bs[4 * fq + 1][col] = breg.y;
                Bs[4 * fq + 2][col] = breg.z;
                Bs[4 * fq + 3][col] = breg.w;
            }
            if (t < 32) w2s[t] = wreg;
        }
        __syncthreads();
        if (k0 + 32 < HDIM) {
            areg = *(const float4*)(g_P + (size_t)(n0 + rr) * HDIM + k0 + 32 + 4 * fq);
            if (t < 256) breg = *(const float4*)(g_P + (size_t)(N_SEG + s0 + rr) * HDIM + k0 + 32 + 4 * fq);
            if (t < 32)  wreg = W2[k0 + 32 + t];
        }
        #pragma unroll
        for (int kk = 0; kk < 32; kk++) {
            int q4 = 4 * (kk >> 2);
            float2 an = *(const float2*)&As[kk][tn ^ q4];
            float2 bv = *(const float2*)&Bs[kk][ts ^ q4];
            float w = w2s[kk];
            acc00 += fmaxf(an.x + bv.x, 0.0f) * w;
            acc01 += fmaxf(an.x + bv.y, 0.0f) * w;
            acc10 += fmaxf(an.y + bv.x, 0.0f) * w;
            acc11 += fmaxf(an.y + bv.y, 0.0f) * w;
        }
    }

    float L[2][2] = {{acc00 + bb2, acc01 + bb2}, {acc10 + bb2, acc11 + bb2}};
    #pragma unroll
    for (int j = 0; j < 2; j++) {
        int s = s0 + ts + j;
        float L0 = L[0][j], L1 = L[1][j];
        *(float2*)&g_logitsT[(size_t)s * N_SEG + n0 + tn] = make_float2(L0, L1);
        float ls0 = fminf(L0, 0.0f) - __logf(1.0f + __expf(-fabsf(L0)));
        float ls1 = fminf(L1, 0.0f) - __logf(1.0f + __expf(-fabsf(L1)));
        *(float2*)&g_logsigT[(size_t)s * N_SEG + n0 + tn] = make_float2(ls0, ls1);
    }
}

// ============================================================
// K3: DP warp = warp 7 (bits inline, hi-wid priority, bubble-filled by
//     co-resident loader warp); warps 0-6 = STS-only loaders (2 ahead).
// ============================================================
template<bool CLAMP>
__device__ __forceinline__ void dp_chunk(const float* __restrict__ buf, int c, int L,
                                         float& p0, float& p1, float& p2, float& p3,
                                         unsigned* __restrict__ rowbits)
{
    unsigned a0 = 0, a1 = 0, a2 = 0, a3 = 0;
    const int n0 = 4 * L;
    #pragma unroll 16
    for (int i = 31; i >= 0; i--) {
        float4 ls = *(const float4*)(buf + i * 128 + n0);
        float nxt3 = __shfl_down_sync(0xffffffffu, p0, 1);
        if (L == 31) nxt3 = 0.0f;               // n=127 adds 0
        float c0 = ls.x + p1;
        float c1 = ls.y + p2;
        float c2 = ls.z + p3;
        float c3 = ls.w + nxt3;
        a0 = a0 + a0 + (unsigned)(c0 >= p0);
        a1 = a1 + a1 + (unsigned)(c1 >= p1);
        a2 = a2 + a2 + (unsigned)(c2 >= p2);
        a3 = a3 + a3 + (unsigned)(c3 >= p3);
        float v0 = fmaxf(c0, p0);
        float v1 = fmaxf(c1, p1);
        float v2 = fmaxf(c2, p2);
        float v3 = fmaxf(c3, p3);
        if (CLAMP) {
            int s = c * 32 + i;
            v0 = (s >= n0     && s <= 1920 + n0) ? v0 : NEGV;
            v1 = (s >= n0 + 1 && s <= 1921 + n0) ? v1 : NEGV;
            v2 = (s >= n0 + 2 && s <= 1922 + n0) ? v2 : NEGV;
            v3 = (s >= n0 + 3 && s <= 1923 + n0) ? v3 : NEGV;
        }
        p0 = v0; p1 = v1; p2 = v2; p3 = v3;
    }
    *(uint4*)(rowbits + c * 128 + n0) = make_uint4(a0, a1, a2, a3);
}

// 224 loader lanes, 1024 float4s per chunk, fully unrolled (MLP 5)
__device__ __forceinline__ void load_chunk(const float4* __restrict__ src,
                                           float4* __restrict__ dst, int lt)
{
    #pragma unroll
    for (int j = 0; j < 5; j++) {
        int i = lt + 224 * j;
        if (i < 1024) dst[i] = src[i];
    }
}

__global__ __launch_bounds__(256) void dp_k3(float* __restrict__ out, int out_size)
{
    extern __shared__ unsigned char smraw[];
    float*    lsbuf    = (float*)smraw;                      // [4][4096]
    unsigned* rowbits  = (unsigned*)(lsbuf + 4 * 4096);      // [64][128]
    int*      alignArr = (int*)(rowbits + 64 * 128);         // [128]
    float*    redbuf   = (float*)(alignArr + 128);           // [4]

    const int t = threadIdx.x;

    if (t < 128) alignArr[t] = 0;
    if (t < 224) {
        load_chunk((const float4*)(g_logsigT + 63 * 4096), (float4*)(lsbuf + 3 * 4096), t);
        load_chunk((const float4*)(g_logsigT + 62 * 4096), (float4*)(lsbuf + 2 * 4096), t);
    }
    __syncthreads();

    float p0 = NEGV, p1 = NEGV, p2 = NEGV, p3 = NEGV;
    for (int c = 63; c >= 0; c--) {
        if (t >= 224) {
            const int L = t - 224;
            const float* buf = lsbuf + (c & 3) * 4096;
            if (c >= 4 && c <= 59) dp_chunk<false>(buf, c, L, p0, p1, p2, p3, rowbits);
            else                   dp_chunk<true >(buf, c, L, p0, p1, p2, p3, rowbits);
        } else {
            if (c >= 2)
                load_chunk((const float4*)(g_logsigT + (size_t)(c - 2) * 4096),
                           (float4*)(lsbuf + ((c - 2) & 3) * 4096), t);
        }
        __syncthreads();
    }

    // walk: first set take-bit at s >= scur per n (equivalent to ref scan)
    if (t == 0) {
        int scur = 0;
        for (int n = 0; n < 128; n++) {
            int w = scur >> 5;
            unsigned word = rowbits[w * 128 + n] & (0xFFFFFFFFu << (scur & 31));
            while (word == 0) {
                w++;
                if (w >= 64) break;
                word = rowbits[w * 128 + n];
            }
            if (w >= 64) break;
            int s = w * 32 + (__ffs(word) - 1);
            alignArr[n] = s;
            scur = s + 1;
            if (scur >= S_VID) break;
        }
    }
    __syncthreads();

    // outputs
    if (t < 128) {
        int a = alignArr[t];
        out[(size_t)(S_VID + t) * RTOT + a] = 1.0f;
        float v = g_logitsT[(size_t)a * N_SEG + t];
        #pragma unroll
        for (int o = 16; o; o >>= 1) v += __shfl_down_sync(0xffffffffu, v, o);
        if ((t & 31) == 0) redbuf[t >> 5] = v;
    }
    __syncthreads();
    if (t == 0) {
        float sum = redbuf[0] + redbuf[1] + redbuf[2] + redbuf[3];
        if (out_size > RTOT * RTOT) out[(size_t)RTOT * RTOT] = sum * (1.0f / 128.0f);
    }
}

// ============================================================
extern "C" void kernel_launch(void* const* d_in, const int* in_sizes, int n_in,
                              void* d_out, int out_size)
{
    const float* seg = (const float*)d_in[0];
    const float* vid = (const float*)d_in[1];
    const float* W1  = (const float*)d_in[2];
    const float* b1  = (const float*)d_in[3];
    const float* W2  = (const float*)d_in[4];
    const float* b2  = (const float*)d_in[5];
    float* out = (float*)d_out;

    cudaMemsetAsync(out, 0, (size_t)out_size * sizeof(float), 0);
    // dummies shift ncu's capture (launch #6) onto dp_k3
    dummy_k<<<1, 32>>>();
    dummy_k<<<1, 32>>>();
    gemm_k1<<<dim3(34, 4), 512>>>(seg, vid, W1, b1);
    fused_k2<<<dim3(2, 64), 512>>>(W2, b2);

    const int smem_k3 = (4 * 4096) * 4 + 64 * 128 * 4 + 128 * 4 + 4 * 4;
    cudaFuncSetAttribute(dp_k3, cudaFuncAttributeMaxDynamicSharedMemorySize, smem_k3);
    dp_k3<<<1, 256, smem_k3>>>(out, out_size);
}